// round 17
// baseline (speedup 1.0000x reference)
#include <cuda_runtime.h>
#include <cuda_fp16.h>
#include <math.h>

// ---------------------------------------------------------------------------
// G_OracleAD: enc-LSTM(+attn pool) -> spatial attention -> dec-LSTM(+readouts)
// B=32 N=64 L=128 H=128  BN=2048  4H=512
// d_out (fp32): recon[262144] | pred[2048] | c_star[262144] | A[131072]
// R17: attention fused into decoder prologue (attn2 kernel + g_cstar gmem
//      round-trip removed; decoder CTA (b, n0) mapping matches attn tiles).
//      3 launches: pack -> encoder -> decoder. LSTM mainloops as R16
//      (cell-in-registers, single-fp16 W, 1 bar/step).
// ---------------------------------------------------------------------------

#define BN_   2048
#define L_    128
#define H_    128
#define G4_   512
#define R_    16
#define NCTA_ (BN_ / R_)   // 128
#define THR_  512
#define GS_   516          // padded gsm row stride (floats)

// device scratch
__device__ uint2  g_encWF[16384];      // fp16x2 B-fragments (permuted cols)
__device__ uint2  g_decWF[16384];
__device__ float4 g_decWihP[32 * G4_];
__device__ float  g_WqT[H_ * H_];
__device__ float  g_WkT[H_ * H_];
__device__ float  g_WvT[H_ * H_];
__device__ float  g_q[BN_ * H_];       // Q rows [bn][d]
__device__ float  g_v[BN_ * H_];       // V rows [bn][d]
__device__ float  g_kT[32 * H_ * 64];  // K transposed [b][d][n]

__device__ __forceinline__ int colorig_(int c) { return (c & 3) * 128 + (c >> 2); }

__device__ __forceinline__ float tanh_(float x) {
    float y;
    asm("tanh.approx.f32 %0, %1;" : "=f"(y) : "f"(x));
    return y;
}
__device__ __forceinline__ float sig_(float x) {
    return fmaf(tanh_(0.5f * x), 0.5f, 0.5f);
}
__device__ __forceinline__ void mma16816h(float* c, unsigned a0, unsigned a1,
                                          unsigned a2, unsigned a3,
                                          unsigned b0, unsigned b1) {
    asm("mma.sync.aligned.m16n8k16.row.col.f32.f16.f16.f32 "
        "{%0,%1,%2,%3}, {%4,%5,%6,%7}, {%8,%9}, {%0,%1,%2,%3};"
        : "+f"(c[0]), "+f"(c[1]), "+f"(c[2]), "+f"(c[3])
        : "r"(a0), "r"(a1), "r"(a2), "r"(a3), "r"(b0), "r"(b1));
}
__device__ __forceinline__ unsigned short f2h_(float w) {
    __half b = __float2half_rn(w);
    return *reinterpret_cast<unsigned short*>(&b);
}
__device__ __forceinline__ int fragidx_(int r, int j) {
    int kt = j >> 4, kl = j & 15;
    int lane_w = ((r & 7) << 2) | ((kl >> 1) & 3);
    int reg    = ((kl >> 3) << 1) | (r >> 3);
    return (((kt * 32 + lane_w) * 4 + reg) << 1) | (kl & 1);
}

// ---------------------------------------------------------------------------
__global__ void pack_kernel(const float* __restrict__ encWhh,
                            const float* __restrict__ decWhh,
                            const float* __restrict__ decWih,
                            const float* __restrict__ Wq,
                            const float* __restrict__ Wk,
                            const float* __restrict__ Wv) {
    int idx = blockIdx.x * blockDim.x + threadIdx.x;   // 0..16383
    {
        int kb = idx >> 9, c = idx & 511;
        int orig = (c & 3) * 128 + (c >> 2);
        int s  = orig * 128 + kb * 4;
        g_decWihP[idx] = make_float4(decWih[s], decWih[s+1], decWih[s+2], decWih[s+3]);
    }
    {
        int nt = idx >> 8, kt = (idx >> 5) & 7, l = idx & 31;
        int c  = nt * 8 + (l >> 2);
        int n  = (c & 3) * 128 + (c >> 2);
        int k0 = kt * 16 + (l & 3) * 2;
        unsigned short h0 = f2h_(encWhh[n * 128 + k0]);
        unsigned short h1 = f2h_(encWhh[n * 128 + k0 + 1]);
        unsigned short h2 = f2h_(encWhh[n * 128 + k0 + 8]);
        unsigned short h3 = f2h_(encWhh[n * 128 + k0 + 9]);
        g_encWF[idx] = make_uint2((unsigned)h0 | ((unsigned)h1 << 16),
                                  (unsigned)h2 | ((unsigned)h3 << 16));
        h0 = f2h_(decWhh[n * 128 + k0]);
        h1 = f2h_(decWhh[n * 128 + k0 + 1]);
        h2 = f2h_(decWhh[n * 128 + k0 + 8]);
        h3 = f2h_(decWhh[n * 128 + k0 + 9]);
        g_decWF[idx] = make_uint2((unsigned)h0 | ((unsigned)h1 << 16),
                                  (unsigned)h2 | ((unsigned)h3 << 16));
    }
    {
        int kk = idx >> 7, d = idx & 127;
        g_WqT[idx] = Wq[d * 128 + kk];
        g_WkT[idx] = Wk[d * 128 + kk];
        g_WvT[idx] = Wv[d * 128 + kk];
    }
}

// ---------------------------------------------------------------------------
// Encoder: tensor-core LSTM + fused online-softmax pool + fused QKV proj.
// smem f-words: gsm 8256 (epilogue c_s) | xs 2112 | red 512 | abuf 2048
// ---------------------------------------------------------------------------
#define ENC_SMEM ((8256 + 2112 + 512 + 2048) * 4)

__global__ __launch_bounds__(THR_, 1)
void encoder_kernel(const float* __restrict__ x,
                    const float* __restrict__ enc_Wih,
                    const float* __restrict__ enc_bih,
                    const float* __restrict__ enc_bhh,
                    const float* __restrict__ pool_w,
                    const float* __restrict__ pool_b,
                    const float* __restrict__ bq,
                    const float* __restrict__ bk,
                    const float* __restrict__ bv) {
    extern __shared__ float smf[];
    float*    gsm  = smf;                      // epilogue c_s
    float*    xs   = gsm + 8256;               // [16][132]
    float*    red  = xs + 2112;                // [2][16][16]
    unsigned* abuf = (unsigned*)(red + 512);   // [2][1024] u32 (fp16 A frags)

    const int tid = threadIdx.x;
    const int w   = tid >> 5, lane = tid & 31;
    const int rowbase = blockIdx.x * R_;

    for (int i = tid; i < 2048;  i += THR_) abuf[i] = 0u;
    for (int i = tid; i < R_ * 128; i += THR_)
        xs[(i >> 7) * 132 + (i & 127)] = x[rowbase * 128 + i];

    uint2 whi[4][8];
    #pragma unroll
    for (int a = 0; a < 4; a++)
        #pragma unroll
        for (int kt = 0; kt < 8; kt++)
            whi[a][kt] = g_encWF[((w * 4 + a) * 8 + kt) * 32 + lane];

    const int row0 = lane >> 2;
    const int colq = (lane & 3) * 2;
    float wihr[8], btr[8];
    #pragma unroll
    for (int a = 0; a < 4; a++)
        #pragma unroll
        for (int hh = 0; hh < 2; hh++) {
            int col  = (w * 4 + a) * 8 + colq + hh;
            int orig = colorig_(col);
            wihr[a * 2 + hh] = enc_Wih[orig];
            btr[a * 2 + hh]  = enc_bih[orig] + enc_bhh[orig];
        }

    // cell-in-registers mapping
    const bool qe   = (lane & 1) == 0;          // pair-even: holds (i,f)
    const int  rowl = (lane >> 2) | ((lane & 1) << 3);
    const float pb = pool_b[0];
    float pw[4];
    int   idxf[4], jg[4];
    #pragma unroll
    for (int a = 0; a < 4; a++) {
        jg[a]   = (w * 4 + a) * 2 + ((lane >> 1) & 1);
        pw[a]   = pool_w[jg[a]];
        idxf[a] = fragidx_(rowl, jg[a]);
    }
    unsigned short* ab16 = (unsigned short*)abuf;

    float cst[4]  = {0.f, 0.f, 0.f, 0.f};
    float accj[4] = {0.f, 0.f, 0.f, 0.f};
    float msx = -INFINITY, zsx = 0.f;

    __syncthreads();

    for (int l = 0; l < L_; l++) {
        const int rp = l & 1;
        const int rbase = rp * 1024;        // u32
        const int wbase = (rp ^ 1) * 2048;  // shorts

        // ---- phase 1: gates on tensor cores (1 MMA/tile) ----
        float acc[4][4];
        float xr0 = xs[row0 * 132 + l];
        float xr8 = xs[(row0 + 8) * 132 + l];
        #pragma unroll
        for (int a = 0; a < 4; a++) {
            acc[a][0] = fmaf(xr0, wihr[a*2],   btr[a*2]);
            acc[a][1] = fmaf(xr0, wihr[a*2+1], btr[a*2+1]);
            acc[a][2] = fmaf(xr8, wihr[a*2],   btr[a*2]);
            acc[a][3] = fmaf(xr8, wihr[a*2+1], btr[a*2+1]);
        }
        #pragma unroll
        for (int kt = 0; kt < 8; kt++) {
            uint4 ah = *(const uint4*)&abuf[rbase + (kt * 32 + lane) * 4];
            #pragma unroll
            for (int a = 0; a < 4; a++)
                mma16816h(acc[a], ah.x, ah.y, ah.z, ah.w, whi[a][kt].x, whi[a][kt].y);
        }

        // ---- phase 2: cell in registers (lane-pair shfl gather) ----
        float hv[4], partial = 0.f;
        #pragma unroll
        for (int a = 0; a < 4; a++) {
            float s0 = qe ? acc[a][2] : acc[a][0];
            float s1 = qe ? acc[a][3] : acc[a][1];
            float r0 = __shfl_xor_sync(0xffffffffu, s0, 1);
            float r1 = __shfl_xor_sync(0xffffffffu, s1, 1);
            float gi = qe ? acc[a][0] : r0;
            float gf = qe ? acc[a][1] : r1;
            float gg = qe ? r0 : acc[a][2];
            float go = qe ? r1 : acc[a][3];
            float si = sig_(gi), sf = sig_(gf), so = sig_(go);
            float tg = tanh_(gg);
            cst[a] = fmaf(sf, cst[a], si * tg);
            float h = so * tanh_(cst[a]);
            hv[a] = h;
            ab16[wbase + idxf[a]] = f2h_(h);
            partial = fmaf(h, pw[a], partial);
        }
        partial += __shfl_xor_sync(0xffffffffu, partial, 2);
        if ((lane & 2) == 0) red[rp * 256 + rowl * 16 + w] = partial;
        __syncthreads();

        // ---- phase 3: replicated online softmax (row = rowl) ----
        {
            const float* rr16 = &red[rp * 256 + rowl * 16];
            float4 v0 = *(const float4*)&rr16[0];
            float4 v1 = *(const float4*)&rr16[4];
            float4 v2 = *(const float4*)&rr16[8];
            float4 v3 = *(const float4*)&rr16[12];
            float s = ((v0.x+v0.y)+(v0.z+v0.w)) + ((v1.x+v1.y)+(v1.z+v1.w))
                    + ((v2.x+v2.y)+(v2.z+v2.w)) + ((v3.x+v3.y)+(v3.z+v3.w)) + pb;
            float mn = fmaxf(msx, s);
            float f  = __expf(msx - mn);
            float wg = __expf(s - mn);
            zsx = zsx * f + wg;
            msx = mn;
            #pragma unroll
            for (int a = 0; a < 4; a++) accj[a] = fmaf(accj[a], f, wg * hv[a]);
        }
    }

    // ---- epilogue A: pooled context c -> smem (reuse gsm as c_s[16][128]) ----
    float* c_s = gsm;
    #pragma unroll
    for (int a = 0; a < 4; a++)
        c_s[rowl * 128 + jg[a]] = __fdividef(accj[a], zsx);
    __syncthreads();

    // ---- epilogue B: fused QKV projection (thread = (row, d4)) ----
    {
        const int r  = tid >> 5;    // 0..15
        const int d4 = tid & 31;    // 0..31
        const float4* WqT4 = reinterpret_cast<const float4*>(g_WqT);
        const float4* WkT4 = reinterpret_cast<const float4*>(g_WkT);
        const float4* WvT4 = reinterpret_cast<const float4*>(g_WvT);
        const float* bq4 = bq + d4 * 4;
        const float* bk4 = bk + d4 * 4;
        const float* bv4 = bv + d4 * 4;
        float4 aq = make_float4(bq4[0], bq4[1], bq4[2], bq4[3]);
        float4 ak = make_float4(bk4[0], bk4[1], bk4[2], bk4[3]);
        float4 av = make_float4(bv4[0], bv4[1], bv4[2], bv4[3]);
        const float* cr = &c_s[r * 128];
        #pragma unroll 4
        for (int kk = 0; kk < 128; kk++) {
            float cv = cr[kk];
            float4 wq = WqT4[kk * 32 + d4];
            float4 wk = WkT4[kk * 32 + d4];
            float4 wv = WvT4[kk * 32 + d4];
            aq.x = fmaf(cv, wq.x, aq.x); aq.y = fmaf(cv, wq.y, aq.y);
            aq.z = fmaf(cv, wq.z, aq.z); aq.w = fmaf(cv, wq.w, aq.w);
            ak.x = fmaf(cv, wk.x, ak.x); ak.y = fmaf(cv, wk.y, ak.y);
            ak.z = fmaf(cv, wk.z, ak.z); ak.w = fmaf(cv, wk.w, ak.w);
            av.x = fmaf(cv, wv.x, av.x); av.y = fmaf(cv, wv.y, av.y);
            av.z = fmaf(cv, wv.z, av.z); av.w = fmaf(cv, wv.w, av.w);
        }
        int bn = rowbase + r;
        *reinterpret_cast<float4*>(&g_q[bn * 128 + d4 * 4]) = aq;
        *reinterpret_cast<float4*>(&g_v[bn * 128 + d4 * 4]) = av;
        int b = bn >> 6, n = bn & 63;
        int dd = d4 * 4;
        g_kT[b * 8192 + (dd + 0) * 64 + n] = ak.x;
        g_kT[b * 8192 + (dd + 1) * 64 + n] = ak.y;
        g_kT[b * 8192 + (dd + 2) * 64 + n] = ak.z;
        g_kT[b * 8192 + (dd + 3) * 64 + n] = ak.w;
    }
}

// ---------------------------------------------------------------------------
// Decoder: fused attention prologue + tensor-core LSTM + readouts.
// smem floats (21504 total = 86 KB):
//   cs [0,2048) | prologue: q_s [2048,4096) kTS [4096,12288) v_s [12288,20480)
//   sc [20480,21504)
//   mainloop (overlaps prologue bufs): gsm [2048,10304) red [10304,10816)
//   red2 [10816,11072) abuf u32 [11072,13120)
// ---------------------------------------------------------------------------
#define DEC_SMEM (21504 * 4)

__global__ __launch_bounds__(THR_, 1)
void decoder_kernel(const float* __restrict__ dec_bih,
                    const float* __restrict__ dec_bhh,
                    const float* __restrict__ rec_w,  const float* __restrict__ rec_b,
                    const float* __restrict__ pred_w, const float* __restrict__ pred_b,
                    float* __restrict__ out_recon, float* __restrict__ out_pred,
                    float* __restrict__ out_cstar, float* __restrict__ out_A) {
    extern __shared__ float smf[];
    float*    cs   = smf;                       // [16][128]
    float*    q_s  = smf + 2048;                // [16][128]
    float*    kTS  = smf + 4096;                // [128][64]
    float*    v_s  = smf + 12288;               // [64][128]
    float*    sc   = smf + 20480;               // [16][64]
    float*    gsm  = smf + 2048;                // [16][516] (after prologue)
    float*    red  = smf + 10304;               // [2][16][16]
    float*    red2 = smf + 10816;               // [16][16]
    unsigned* abuf = (unsigned*)(smf + 11072);  // [2][1024] u32

    const int tid = threadIdx.x;
    const int w   = tid >> 5, lane = tid & 31;
    const int rowbase = blockIdx.x * R_;
    const int bb  = blockIdx.x >> 2;            // batch
    const int n0  = (blockIdx.x & 3) * 16;      // Q-row tile base

    // ================= attention prologue (was attn2_kernel) =================
    {
        const float4* q4 = reinterpret_cast<const float4*>(g_q + bb * 8192 + n0 * 128);
        const float4* k4 = reinterpret_cast<const float4*>(g_kT + bb * 8192);
        const float4* v4 = reinterpret_cast<const float4*>(g_v + bb * 8192);
        for (int i = tid; i < 512;  i += THR_) *reinterpret_cast<float4*>(&q_s[i * 4]) = q4[i];
        for (int i = tid; i < 2048; i += THR_) *reinterpret_cast<float4*>(&kTS[i * 4]) = k4[i];
        for (int i = tid; i < 2048; i += THR_) *reinterpret_cast<float4*>(&v_s[i * 4]) = v4[i];
    }
    __syncthreads();

    {
        const float scale = 0.08838834764831845f;   // 1/sqrt(128)
        for (int o = tid; o < 1024; o += THR_) {
            int n = o >> 6, m = o & 63;
            float s = 0.f;
            const float* qr = &q_s[n * 128];
            #pragma unroll 8
            for (int d = 0; d < 128; d++) s = fmaf(qr[d], kTS[d * 64 + m], s);
            sc[o] = s * scale;
        }
    }
    __syncthreads();

    if (w < 16) {
        int n = w;
        float v0 = sc[n * 64 + lane], v1 = sc[n * 64 + 32 + lane];
        float mx = fmaxf(v0, v1);
        #pragma unroll
        for (int o = 16; o; o >>= 1) mx = fmaxf(mx, __shfl_xor_sync(0xffffffffu, mx, o));
        float e0 = __expf(v0 - mx), e1 = __expf(v1 - mx);
        float ss = e0 + e1;
        #pragma unroll
        for (int o = 16; o; o >>= 1) ss += __shfl_xor_sync(0xffffffffu, ss, o);
        float inv = 1.f / ss;
        float a0 = e0 * inv, a1 = e1 * inv;
        sc[n * 64 + lane] = a0;
        sc[n * 64 + 32 + lane] = a1;
        out_A[bb * 4096 + (n0 + n) * 64 + lane] = a0;
        out_A[bb * 4096 + (n0 + n) * 64 + 32 + lane] = a1;
    }
    __syncthreads();

    for (int o = tid; o < 2048; o += THR_) {
        int n = o >> 7, d = o & 127;
        float s = 0.f;
        const float* ar = &sc[n * 64];
        #pragma unroll 8
        for (int m = 0; m < 64; m++) s = fmaf(ar[m], v_s[m * 128 + d], s);
        out_cstar[bb * 8192 + (n0 + n) * 128 + d] = s;
        cs[n * 128 + d] = s;
    }
    __syncthreads();
    // ================= end attention prologue =================

    for (int i = tid; i < 2048; i += THR_) abuf[i] = 0u;

    uint2 whi[4][8];
    #pragma unroll
    for (int a = 0; a < 4; a++)
        #pragma unroll
        for (int kt = 0; kt < 8; kt++)
            whi[a][kt] = g_decWF[((w * 4 + a) * 8 + kt) * 32 + lane];

    const int row0 = lane >> 2;
    const int colq = (lane & 3) * 2;

    // cell-in-registers mapping
    const bool qe   = (lane & 1) == 0;
    const int  rowl = (lane >> 2) | ((lane & 1) << 3);
    const float rbv = rec_b[0], pbv = pred_b[0];
    float rw[4], pw2[4];
    int   idxf[4];
    #pragma unroll
    for (int a = 0; a < 4; a++) {
        int jga = (w * 4 + a) * 2 + ((lane >> 1) & 1);
        rw[a]   = rec_w[jga];
        pw2[a]  = pred_w[jga];
        idxf[a] = fragidx_(rowl, jga);
    }
    unsigned short* ab16 = (unsigned short*)abuf;

    float cst[4] = {0.f, 0.f, 0.f, 0.f};
    __syncthreads();

    // ---- dpr GEMM (scalar, once): thread = permuted col tid; via gsm ----
    {
        const int orig = colorig_(tid);
        const float bt = dec_bih[orig] + dec_bhh[orig];
        float dpr[R_];
        #pragma unroll
        for (int r = 0; r < R_; r++) dpr[r] = bt;
        #pragma unroll 4
        for (int kb = 0; kb < 32; kb++) {
            float4 wv = g_decWihP[kb * G4_ + tid];
            #pragma unroll
            for (int r = 0; r < R_; r++) {
                float4 h4 = *reinterpret_cast<const float4*>(&cs[r * 128 + kb * 4]);
                dpr[r] = fmaf(wv.x, h4.x, dpr[r]);
                dpr[r] = fmaf(wv.y, h4.y, dpr[r]);
                dpr[r] = fmaf(wv.z, h4.z, dpr[r]);
                dpr[r] = fmaf(wv.w, h4.w, dpr[r]);
            }
        }
        #pragma unroll
        for (int r = 0; r < R_; r++) gsm[r * GS_ + tid] = dpr[r];
    }
    __syncwarp();

    float dfrag[4][4];
    #pragma unroll
    for (int a = 0; a < 4; a++) {
        int cb = (w * 4 + a) * 8 + colq;
        float2 d0 = *(const float2*)&gsm[row0 * GS_ + cb];
        float2 d8 = *(const float2*)&gsm[(row0 + 8) * GS_ + cb];
        dfrag[a][0] = d0.x; dfrag[a][1] = d0.y;
        dfrag[a][2] = d8.x; dfrag[a][3] = d8.y;
    }
    __syncwarp();

    for (int l = 0; l < L_; l++) {
        const int rp = l & 1;
        const int rbase = rp * 1024;
        const int wbase = (rp ^ 1) * 2048;

        // ---- phase 1: gates on tensor cores (1 MMA/tile) ----
        float acc[4][4];
        #pragma unroll
        for (int a = 0; a < 4; a++)
            #pragma unroll
            for (int q = 0; q < 4; q++) acc[a][q] = dfrag[a][q];
        #pragma unroll
        for (int kt = 0; kt < 8; kt++) {
            uint4 ah = *(const uint4*)&abuf[rbase + (kt * 32 + lane) * 4];
            #pragma unroll
            for (int a = 0; a < 4; a++)
                mma16816h(acc[a], ah.x, ah.y, ah.z, ah.w, whi[a][kt].x, whi[a][kt].y);
        }

        // ---- phase 2: cell in registers + readout partials ----
        float partial = 0.f, partial2 = 0.f;
        #pragma unroll
        for (int a = 0; a < 4; a++) {
            float s0 = qe ? acc[a][2] : acc[a][0];
            float s1 = qe ? acc[a][3] : acc[a][1];
            float r0 = __shfl_xor_sync(0xffffffffu, s0, 1);
            float r1 = __shfl_xor_sync(0xffffffffu, s1, 1);
            float gi = qe ? acc[a][0] : r0;
            float gf = qe ? acc[a][1] : r1;
            float gg = qe ? r0 : acc[a][2];
            float go = qe ? r1 : acc[a][3];
            float si = sig_(gi), sf = sig_(gf), so = sig_(go);
            float tg = tanh_(gg);
            cst[a] = fmaf(sf, cst[a], si * tg);
            float h = so * tanh_(cst[a]);
            ab16[wbase + idxf[a]] = f2h_(h);
            partial = fmaf(h, rw[a], partial);
            if (l == L_ - 1) partial2 = fmaf(h, pw2[a], partial2);
        }
        partial += __shfl_xor_sync(0xffffffffu, partial, 2);
        if ((lane & 2) == 0) red[rp * 256 + rowl * 16 + w] = partial;
        if (l == L_ - 1) {
            partial2 += __shfl_xor_sync(0xffffffffu, partial2, 2);
            if ((lane & 2) == 0) red2[rowl * 16 + w] = partial2;
        }
        __syncthreads();

        // ---- phase 3: leaders write recon (and pred last step) ----
        if (tid < 16) {
            const float* r16 = &red[rp * 256 + tid * 16];
            float4 v0 = *(const float4*)&r16[0];
            float4 v1 = *(const float4*)&r16[4];
            float4 v2 = *(const float4*)&r16[8];
            float4 v3 = *(const float4*)&r16[12];
            float s = ((v0.x+v0.y)+(v0.z+v0.w)) + ((v1.x+v1.y)+(v1.z+v1.w))
                    + ((v2.x+v2.y)+(v2.z+v2.w)) + ((v3.x+v3.y)+(v3.z+v3.w)) + rbv;
            out_recon[(rowbase + tid) * 128 + l] = s;
            if (l == L_ - 1) {
                const float* q16 = &red2[tid * 16];
                float4 u0 = *(const float4*)&q16[0];
                float4 u1 = *(const float4*)&q16[4];
                float4 u2 = *(const float4*)&q16[8];
                float4 u3 = *(const float4*)&q16[12];
                float p2 = ((u0.x+u0.y)+(u0.z+u0.w)) + ((u1.x+u1.y)+(u1.z+u1.w))
                         + ((u2.x+u2.y)+(u2.z+u2.w)) + ((u3.x+u3.y)+(u3.z+u3.w)) + pbv;
                out_pred[rowbase + tid] = p2;
            }
        }
    }
}

// ---------------------------------------------------------------------------
extern "C" void kernel_launch(void* const* d_in, const int* in_sizes, int n_in,
                              void* d_out, int out_size) {
    const float* x        = (const float*)d_in[0];
    const float* enc_Wih  = (const float*)d_in[1];
    const float* enc_Whh  = (const float*)d_in[2];
    const float* enc_bih  = (const float*)d_in[3];
    const float* enc_bhh  = (const float*)d_in[4];
    const float* pool_w   = (const float*)d_in[5];
    const float* pool_b   = (const float*)d_in[6];
    const float* Wq       = (const float*)d_in[7];
    const float* bq       = (const float*)d_in[8];
    const float* Wk       = (const float*)d_in[9];
    const float* bk       = (const float*)d_in[10];
    const float* Wv       = (const float*)d_in[11];
    const float* bv       = (const float*)d_in[12];
    const float* dec_Wih  = (const float*)d_in[13];
    const float* dec_Whh  = (const float*)d_in[14];
    const float* dec_bih  = (const float*)d_in[15];
    const float* dec_bhh  = (const float*)d_in[16];
    const float* rec_w    = (const float*)d_in[17];
    const float* rec_b    = (const float*)d_in[18];
    const float* pred_w   = (const float*)d_in[19];
    const float* pred_b   = (const float*)d_in[20];

    float* out = (float*)d_out;
    float* out_recon = out;
    float* out_pred  = out + 262144;
    float* out_cstar = out + 264192;
    float* out_A     = out + 526336;

    cudaFuncSetAttribute(encoder_kernel, cudaFuncAttributeMaxDynamicSharedMemorySize, ENC_SMEM);
    cudaFuncSetAttribute(decoder_kernel, cudaFuncAttributeMaxDynamicSharedMemorySize, DEC_SMEM);

    pack_kernel<<<64, 256>>>(enc_Whh, dec_Whh, dec_Wih, Wq, Wk, Wv);
    encoder_kernel<<<NCTA_, THR_, ENC_SMEM>>>(x, enc_Wih, enc_bih, enc_bhh,
                                              pool_w, pool_b, bq, bk, bv);
    decoder_kernel<<<NCTA_, THR_, DEC_SMEM>>>(dec_bih, dec_bhh, rec_w, rec_b,
                                              pred_w, pred_b, out_recon, out_pred,
                                              out_cstar, out_A);
}